// round 16
// baseline (speedup 1.0000x reference)
#include <cuda_runtime.h>
#include <cstdint>
#include <math.h>

// Problem constants
#define PP 128
#define LL 800
#define DD 200
#define HH 100
#define MM 256        // P*K
#define MB 255        // M-1

// Output offsets (floats)
#define OFF_SCS 0
#define OFF_R   40960000          // M*L*D
#define OFF_ENC 40985600          // +M*H
#define OFF_V   41190400          // +M*L
#define OFF_T   41255680          // +M*(M-1)

#define SEG_ROWS 50               // t-rows per copy job
#define NJOBS 4096                // 256 m * 16 segments
#define GRID 888                  // 148 SMs * 6 resident -> single wave
#define ZBYTES 16384              // SMEM zero buffer (16 KB)

// Scratch
__device__ float g_cT[HH * MM];   // transposed: [h][m]
__device__ float g_o[MM * HH];
__device__ float g_alpha[MM * MB];
__device__ float g_colA[MB];
__device__ int   g_job;           // steal queue head
__device__ int   g_cnt1;          // p1 completion count
__device__ int   g_cnt2;          // p2 completion count
__device__ int   g_done;          // exit count (for self-reset)

__device__ __forceinline__ float fast_tanh(float x) {
    float y;
    asm("tanh.approx.f32 %0, %1;" : "=f"(y) : "f"(x));
    return y;
}

__device__ __forceinline__ float warp_sum(float v) {
    #pragma unroll
    for (int o = 16; o; o >>= 1) v += __shfl_down_sync(0xffffffffu, v, o);
    return v;
}

__device__ __forceinline__ uint32_t smem_u32(const void* p) {
    uint32_t a;
    asm("{ .reg .u64 t; cvta.to.shared.u64 t, %1; cvt.u32.u64 %0, t; }"
        : "=r"(a) : "l"(p));
    return a;
}

// Bulk-zero [dst, dst+bytes) via TMA stores from the SMEM zero buffer.
// Single-thread issue; bytes is a multiple of 16.
__device__ __forceinline__ void bulk_zero(float* dst, int bytes, uint32_t zbuf) {
    while (bytes > 0) {
        int n = bytes > ZBYTES ? ZBYTES : bytes;
        asm volatile("cp.async.bulk.global.shared::cta.bulk_group [%0], [%1], %2;"
                     :: "l"(dst), "r"(zbuf), "r"(n) : "memory");
        dst   += n >> 2;
        bytes -= n;
    }
}

// Masked copy of S_p rows into S_Cs for (m, t in [t0, t0+SEG_ROWS)).
// Zero prefix/suffix: TMA bulk stores (1-2 instructions per range).
// Copy middle: batch-4 default LDG.128 (keeps S_p L2-resident) + __stcs stores.
__device__ __forceinline__ void copy_job(int job, const float* __restrict__ S_p,
                                         const int* __restrict__ spans,
                                         float* __restrict__ out, uint32_t zbuf) {
    int m  = job >> 4;
    int t0 = (job & 15) * SEG_ROWS;
    int t1 = t0 + SEG_ROWS;
    int st = spans[2 * m];
    int en = spans[2 * m + 1];
    int p  = m >> 1;
    int c0 = max(st, t0);
    int c1 = min(en + 1, t1);
    if (c0 >= c1) { c0 = t0; c1 = t0; }

    const float4* __restrict__ src = (const float4*)(S_p + (size_t)p * LL * DD);
    float4* __restrict__ dst = (float4*)(out + (size_t)m * LL * DD);
    int tid = threadIdx.x;
    int lo0 = t0 * 50, s_lo = c0 * 50, s_hi = c1 * 50, hi1 = t1 * 50;

    if (tid == 0) {
        // zero-prefix rows [t0,c0), zero-suffix rows [c1,t1): TMA bulk stores
        if (s_lo > lo0) bulk_zero((float*)(dst + lo0), (s_lo - lo0) * 16, zbuf);
        if (hi1 > s_hi) bulk_zero((float*)(dst + s_hi), (hi1 - s_hi) * 16, zbuf);
        asm volatile("cp.async.bulk.commit_group;" ::: "memory");
        // bound outstanding groups
        asm volatile("cp.async.bulk.wait_group 16;" ::: "memory");
    }
    // copy-middle: explicit batch-4 (4 independent LDG.128 before any STG)
    int i = s_lo + tid;
    for (; i + 768 < s_hi; i += 1024) {
        float4 v0 = src[i];
        float4 v1 = src[i + 256];
        float4 v2 = src[i + 512];
        float4 v3 = src[i + 768];
        __stcs(&dst[i],       v0);
        __stcs(&dst[i + 256], v1);
        __stcs(&dst[i + 512], v2);
        __stcs(&dst[i + 768], v3);
    }
    for (; i < s_hi; i += 256) __stcs(&dst[i], src[i]);
}

// Try to steal one job. Returns false when queue empty. Block-uniform.
__device__ __forceinline__ bool steal_one(const float* __restrict__ S_p,
                                          const int* __restrict__ spans,
                                          float* __restrict__ out,
                                          int* s_tmp, uint32_t zbuf) {
    if (threadIdx.x == 0) *s_tmp = atomicAdd(&g_job, 1);
    __syncthreads();
    int job = *s_tmp;
    __syncthreads();
    if (job >= NJOBS) return false;
    copy_job(job, S_p, spans, out, zbuf);
    return true;
}

// Wait until *cnt >= target, stealing copy jobs while waiting.
__device__ __forceinline__ void wait_phase(volatile int* cnt, int target,
                                           const float* __restrict__ S_p,
                                           const int* __restrict__ spans,
                                           float* __restrict__ out,
                                           int* s_tmp, uint32_t zbuf) {
    for (;;) {
        if (threadIdx.x == 0) *s_tmp = (*cnt >= target) ? -1 : 0;
        __syncthreads();
        int ok = *s_tmp;
        __syncthreads();
        if (ok) break;
        steal_one(S_p, spans, out, s_tmp, zbuf);   // spins cheaply once queue empty
    }
    __threadfence();
    __syncthreads();
}

// ---------------- phase 1 compute: r, c, o, enc for row m (single-h, lean regs) ----------------
__device__ void phase1(int m, const float* __restrict__ S_p,
                       const int* __restrict__ spans,
                       const int* __restrict__ passages,
                       const float* __restrict__ Wb, const float* __restrict__ We,
                       const float* __restrict__ Wc, const float* __restrict__ Wo,
                       float* __restrict__ out,
                       float* sb, float* se, float* rs) {
    int tid = threadIdx.x;
    int st = spans[2 * m];
    int en = spans[2 * m + 1];
    int p  = m >> 1;
    const float* rowb = S_p + ((size_t)p * LL + st) * DD;
    const float* rowe = S_p + ((size_t)p * LL + en) * DD;
    for (int i = tid; i < DD; i += 256) { sb[i] = rowb[i]; se[i] = rowe[i]; }
    __syncthreads();
    int warp = tid >> 5, lane = tid & 31;
    // r[h] = tanh(sb.Wb[h] + se.We[h]) — warp per h, coalesced weight reads
    for (int h = warp; h < HH; h += 8) {
        const float* wb = Wb + h * DD;
        const float* we = We + h * DD;
        float a = 0.f;
        #pragma unroll
        for (int d = lane; d < DD; d += 32) a += sb[d] * wb[d] + se[d] * we[d];
        a = warp_sum(a);
        if (lane == 0) {
            float r = fast_tanh(a);
            rs[h] = r;
            out[OFF_R + m * HH + h] = r;
        }
    }
    __syncthreads();
    // c[h] = r.Wc[h], o[h] = r.Wo[h]
    for (int h = warp; h < HH; h += 8) {
        const float* wc = Wc + h * HH;
        const float* wo = Wo + h * HH;
        float ca = 0.f, oa = 0.f;
        #pragma unroll
        for (int j = lane; j < HH; j += 32) {
            float r = rs[j];
            ca += r * wc[j];
            oa += r * wo[j];
        }
        ca = warp_sum(ca);
        oa = warp_sum(oa);
        if (lane == 0) {
            g_cT[h * MM + m] = ca;
            g_o[m * HH + h] = oa;
        }
    }
    // encoded_candidates (independent)
    int len = en - st;
    for (int t = tid; t < LL; t += 256) {
        out[OFF_ENC + m * LL + t] =
            (t <= len) ? (float)passages[p * LL + st + t] : 0.0f;
    }
    __syncthreads();
}

// ---------------- phase 2 compute: V column b + alpha + colA ----------------
__device__ void phase2(int b, const float* __restrict__ Wv,
                       float* __restrict__ out,
                       float* so0, float* so1, float* wv, float* red) {
    int tid = threadIdx.x;
    if (tid < HH) {
        so0[tid] = g_o[b * HH + tid];
        so1[tid] = g_o[(b + 1) * HH + tid];
        wv[tid]  = Wv[tid];
    }
    __syncthreads();
    int m = tid;
    const float* oo = (b >= m) ? so1 : so0;
    float acc = 0.f;
    #pragma unroll 8
    for (int h = 0; h < HH; h++)
        acc += fast_tanh(g_cT[h * MM + m] + oo[h]) * wv[h];
    out[OFF_V + m * MB + b] = acc;
    float e = __expf(acc);
    red[tid] = e;
    __syncthreads();
    for (int s = 128; s > 0; s >>= 1) {
        if (tid < s) red[tid] += red[tid + s];
        __syncthreads();
    }
    float sumE = red[0];
    __syncthreads();
    float a = e / (sumE - e);
    g_alpha[m * MB + b] = a;
    red[tid] = a;
    __syncthreads();
    for (int s = 128; s > 0; s >>= 1) {
        if (tid < s) red[tid] += red[tid + s];
        __syncthreads();
    }
    if (tid == 0) g_colA[b] = red[0];
    __syncthreads();
}

// ---------------- phase 3 compute: tilda row m ----------------
__device__ void phase3(int m, float* __restrict__ out, float* sr, float* partial) {
    int tid = threadIdx.x;
    if (tid < MB) sr[tid] = g_colA[tid] - g_alpha[m * MB + tid];
    __syncthreads();
    int half = tid >> 7;
    int h    = tid & 127;
    float acc = 0.f;
    if (h < HH) {
        const float* rbase = out + OFF_R;
        int b0 = half ? 128 : 0;
        int b1 = half ? MB : 128;
        #pragma unroll 4
        for (int b = b0; b < b1; b++) {
            int j = b + (b >= m);
            acc += sr[b] * rbase[j * HH + h];
        }
    }
    if (half == 0 && h < HH) partial[h] = acc;
    __syncthreads();
    if (half == 1 && h < HH) out[OFF_T + m * HH + h] = acc + partial[h];
    __syncthreads();
}

// ---------------- single persistent kernel ----------------
__global__ __launch_bounds__(256, 6) void kAll(const float* __restrict__ S_p,
                                               const int* __restrict__ spans,
                                               const int* __restrict__ passages,
                                               const float* __restrict__ Wb,
                                               const float* __restrict__ We,
                                               const float* __restrict__ Wc,
                                               const float* __restrict__ Wo,
                                               const float* __restrict__ Wv,
                                               float* __restrict__ out) {
    __shared__ __align__(16) float4 zblk[ZBYTES / 16];   // zeros for TMA stores
    __shared__ float shA[2 * DD];          // sb|se (p1) ; so0|so1+wv (p2)
    __shared__ float shB[MM + 8];          // rs (p1) ; red (p2) ; sr (p3)
    __shared__ float shC[HH + 4];          // partial (p3)
    __shared__ int   s_tmp;
    int bid = blockIdx.x;
    int tid = threadIdx.x;

    // init zero buffer once; fence for async-proxy reads (TMA)
    const float4 z = make_float4(0.f, 0.f, 0.f, 0.f);
    #pragma unroll
    for (int i = tid; i < ZBYTES / 16; i += 256) zblk[i] = z;
    asm volatile("fence.proxy.async.shared::cta;" ::: "memory");
    __syncthreads();
    uint32_t zbuf = smem_u32(zblk);

    if (bid < MM) {
        // p1 block for row m=bid
        phase1(bid, S_p, spans, passages, Wb, We, Wc, Wo, out,
               shA, shA + DD, shB);
        __threadfence();
        if (tid == 0) atomicAdd(&g_cnt1, 1);
        __syncthreads();
    } else if (bid < MM + MB) {
        // p2 block for column b=bid-256: wait for all p1, stealing meanwhile
        wait_phase(&g_cnt1, MM, S_p, spans, out, &s_tmp, zbuf);
        phase2(bid - MM, Wv, out, shA, shA + HH, shA + 2 * HH, shB);
        __threadfence();
        if (tid == 0) atomicAdd(&g_cnt2, 1);
        __syncthreads();
    }

    if (bid < MM) {
        // p3 reuses p1 blocks: wait for all p2, stealing meanwhile
        wait_phase(&g_cnt2, MB, S_p, spans, out, &s_tmp, zbuf);
        phase3(bid, out, shB, shC);
    }

    // drain remaining copy jobs
    while (steal_one(S_p, spans, out, &s_tmp, zbuf)) {}

    // all TMA bulk stores must complete before kernel exit
    if (tid == 0) asm volatile("cp.async.bulk.wait_group 0;" ::: "memory");

    // exit + self-reset for graph replay
    __syncthreads();
    if (tid == 0) {
        int d = atomicAdd(&g_done, 1);
        if (d == GRID - 1) {
            g_job  = 0;
            g_cnt1 = 0;
            g_cnt2 = 0;
            g_done = 0;
        }
    }
}

extern "C" void kernel_launch(void* const* d_in, const int* in_sizes, int n_in,
                              void* d_out, int out_size) {
    const float* S_p      = (const float*)d_in[0];
    const int*   spans    = (const int*)d_in[1];
    const int*   passages = (const int*)d_in[2];
    const float* Wb       = (const float*)d_in[3];
    const float* We       = (const float*)d_in[4];
    const float* Wc       = (const float*)d_in[5];
    const float* Wo       = (const float*)d_in[6];
    const float* Wv       = (const float*)d_in[7];
    float* out = (float*)d_out;

    kAll<<<GRID, 256>>>(S_p, spans, passages, Wb, We, Wc, Wo, Wv, out);
}

// round 17
// speedup vs baseline: 1.2671x; 1.2671x over previous
#include <cuda_runtime.h>
#include <cstdint>
#include <math.h>

// Problem constants
#define PP 128
#define LL 800
#define DD 200
#define HH 100
#define MM 256        // P*K
#define MB 255        // M-1

// Output offsets (floats)
#define OFF_SCS 0
#define OFF_R   40960000          // M*L*D
#define OFF_ENC 40985600          // +M*H
#define OFF_V   41190400          // +M*L
#define OFF_T   41255680          // +M*(M-1)

#define SEG_ROWS 50               // t-rows per copy job
#define NJOBS 4096                // 256 m * 16 segments
#define GRID 740                  // 148 SMs * 5 resident -> single wave
#define ZBYTES 32768              // SMEM zero buffer (32 KB)

// Scratch
__device__ float g_cT[HH * MM];   // transposed: [h][m]
__device__ float g_o[MM * HH];
__device__ float g_alpha[MM * MB];
__device__ float g_colA[MB];
__device__ int   g_job;           // steal queue head
__device__ int   g_cnt1;          // p1 completion count
__device__ int   g_cnt2;          // p2 completion count
__device__ int   g_done;          // exit count (for self-reset)

__device__ __forceinline__ float fast_tanh(float x) {
    float y;
    asm("tanh.approx.f32 %0, %1;" : "=f"(y) : "f"(x));
    return y;
}

__device__ __forceinline__ float warp_sum(float v) {
    #pragma unroll
    for (int o = 16; o; o >>= 1) v += __shfl_down_sync(0xffffffffu, v, o);
    return v;
}

__device__ __forceinline__ uint32_t smem_u32(const void* p) {
    uint32_t a;
    asm("{ .reg .u64 t; cvta.to.shared.u64 t, %1; cvt.u32.u64 %0, t; }"
        : "=r"(a) : "l"(p));
    return a;
}

// Bulk-zero [dst, dst+bytes) via TMA stores from the SMEM zero buffer.
// Single-thread issue; bytes is a multiple of 16.
__device__ __forceinline__ void bulk_zero(float* dst, int bytes, uint32_t zbuf) {
    while (bytes > 0) {
        int n = bytes > ZBYTES ? ZBYTES : bytes;
        asm volatile("cp.async.bulk.global.shared::cta.bulk_group [%0], [%1], %2;"
                     :: "l"(dst), "r"(zbuf), "r"(n) : "memory");
        dst   += n >> 2;
        bytes -= n;
    }
}

// Masked copy of S_p rows into S_Cs for (m, t in [t0, t0+SEG_ROWS)).
// Zero prefix/suffix: TMA bulk stores (1-2 instructions per range).
// Copy middle: batch-4 LDG.128 (default policy keeps S_p L2-resident)
// + __stcs streaming stores (evict-first write stream).
__device__ __forceinline__ void copy_job(int job, const float* __restrict__ S_p,
                                         const int* __restrict__ spans,
                                         float* __restrict__ out, uint32_t zbuf) {
    int m  = job >> 4;
    int t0 = (job & 15) * SEG_ROWS;
    int t1 = t0 + SEG_ROWS;
    int st = spans[2 * m];
    int en = spans[2 * m + 1];
    int p  = m >> 1;
    int c0 = max(st, t0);
    int c1 = min(en + 1, t1);
    if (c0 >= c1) { c0 = t0; c1 = t0; }

    const float4* __restrict__ src = (const float4*)(S_p + (size_t)p * LL * DD);
    float4* __restrict__ dst = (float4*)(out + (size_t)m * LL * DD);
    int tid = threadIdx.x;
    int lo0 = t0 * 50, s_lo = c0 * 50, s_hi = c1 * 50, hi1 = t1 * 50;

    if (tid == 0) {
        // zero-prefix rows [t0,c0), zero-suffix rows [c1,t1): TMA bulk stores
        if (s_lo > lo0) bulk_zero((float*)(dst + lo0), (s_lo - lo0) * 16, zbuf);
        if (hi1 > s_hi) bulk_zero((float*)(dst + s_hi), (hi1 - s_hi) * 16, zbuf);
        asm volatile("cp.async.bulk.commit_group;" ::: "memory");
        // bound outstanding groups
        asm volatile("cp.async.bulk.wait_group 16;" ::: "memory");
    }
    // copy-middle: explicit batch-4 (4 independent LDG.128 before any STG)
    int i = s_lo + tid;
    for (; i + 768 < s_hi; i += 1024) {
        float4 v0 = src[i];
        float4 v1 = src[i + 256];
        float4 v2 = src[i + 512];
        float4 v3 = src[i + 768];
        __stcs(&dst[i],       v0);
        __stcs(&dst[i + 256], v1);
        __stcs(&dst[i + 512], v2);
        __stcs(&dst[i + 768], v3);
    }
    for (; i < s_hi; i += 256) __stcs(&dst[i], src[i]);
}

// Try to steal one job. Returns false when queue empty. Block-uniform.
__device__ __forceinline__ bool steal_one(const float* __restrict__ S_p,
                                          const int* __restrict__ spans,
                                          float* __restrict__ out,
                                          int* s_tmp, uint32_t zbuf) {
    if (threadIdx.x == 0) *s_tmp = atomicAdd(&g_job, 1);
    __syncthreads();
    int job = *s_tmp;
    __syncthreads();
    if (job >= NJOBS) return false;
    copy_job(job, S_p, spans, out, zbuf);
    return true;
}

// Wait until *cnt >= target, stealing copy jobs while waiting.
__device__ __forceinline__ void wait_phase(volatile int* cnt, int target,
                                           const float* __restrict__ S_p,
                                           const int* __restrict__ spans,
                                           float* __restrict__ out,
                                           int* s_tmp, uint32_t zbuf) {
    for (;;) {
        if (threadIdx.x == 0) *s_tmp = (*cnt >= target) ? -1 : 0;
        __syncthreads();
        int ok = *s_tmp;
        __syncthreads();
        if (ok) break;
        steal_one(S_p, spans, out, s_tmp, zbuf);   // spins cheaply once queue empty
    }
    __threadfence();
    __syncthreads();
}

// ---------------- phase 1 compute: r, c, o, enc for row m ----------------
__device__ void phase1(int m, const float* __restrict__ S_p,
                       const int* __restrict__ spans,
                       const int* __restrict__ passages,
                       const float* __restrict__ Wb, const float* __restrict__ We,
                       const float* __restrict__ Wc, const float* __restrict__ Wo,
                       float* __restrict__ out,
                       float* sb, float* se, float* rs) {
    int tid = threadIdx.x;
    int st = spans[2 * m];
    int en = spans[2 * m + 1];
    int p  = m >> 1;
    const float* rowb = S_p + ((size_t)p * LL + st) * DD;
    const float* rowe = S_p + ((size_t)p * LL + en) * DD;
    for (int i = tid; i < DD; i += 256) { sb[i] = rowb[i]; se[i] = rowe[i]; }
    __syncthreads();
    int warp = tid >> 5, lane = tid & 31;
    for (int hh = warp; hh < HH; hh += 16) {
        int hB = hh + 8;
        float a0 = 0.f, a1 = 0.f;
        const float* wb0 = Wb + hh * DD;
        const float* we0 = We + hh * DD;
        if (hB < HH) {
            const float* wb1 = Wb + hB * DD;
            const float* we1 = We + hB * DD;
            #pragma unroll
            for (int d = lane; d < DD; d += 32) {
                float bs = sb[d], es = se[d];
                a0 += bs * wb0[d] + es * we0[d];
                a1 += bs * wb1[d] + es * we1[d];
            }
        } else {
            #pragma unroll
            for (int d = lane; d < DD; d += 32)
                a0 += sb[d] * wb0[d] + se[d] * we0[d];
        }
        a0 = warp_sum(a0);
        a1 = warp_sum(a1);
        if (lane == 0) {
            float r0 = fast_tanh(a0);
            rs[hh] = r0;
            out[OFF_R + m * HH + hh] = r0;
            if (hB < HH) {
                float r1 = fast_tanh(a1);
                rs[hB] = r1;
                out[OFF_R + m * HH + hB] = r1;
            }
        }
    }
    __syncthreads();
    for (int hh = warp; hh < HH; hh += 16) {
        int hB = hh + 8;
        float c0 = 0.f, o0 = 0.f, c1v = 0.f, o1v = 0.f;
        const float* wc0 = Wc + hh * HH;
        const float* wo0 = Wo + hh * HH;
        if (hB < HH) {
            const float* wc1 = Wc + hB * HH;
            const float* wo1 = Wo + hB * HH;
            #pragma unroll
            for (int j = lane; j < HH; j += 32) {
                float r = rs[j];
                c0  += r * wc0[j];
                o0  += r * wo0[j];
                c1v += r * wc1[j];
                o1v += r * wo1[j];
            }
        } else {
            #pragma unroll
            for (int j = lane; j < HH; j += 32) {
                float r = rs[j];
                c0 += r * wc0[j];
                o0 += r * wo0[j];
            }
        }
        c0  = warp_sum(c0);
        o0  = warp_sum(o0);
        c1v = warp_sum(c1v);
        o1v = warp_sum(o1v);
        if (lane == 0) {
            g_cT[hh * MM + m] = c0;
            g_o[m * HH + hh] = o0;
            if (hB < HH) {
                g_cT[hB * MM + m] = c1v;
                g_o[m * HH + hB] = o1v;
            }
        }
    }
    int len = en - st;
    for (int t = tid; t < LL; t += 256) {
        out[OFF_ENC + m * LL + t] =
            (t <= len) ? (float)passages[p * LL + st + t] : 0.0f;
    }
    __syncthreads();
}

// ---------------- phase 2 compute: V column b + alpha + colA ----------------
__device__ void phase2(int b, const float* __restrict__ Wv,
                       float* __restrict__ out,
                       float* so0, float* so1, float* wv, float* red) {
    int tid = threadIdx.x;
    if (tid < HH) {
        so0[tid] = g_o[b * HH + tid];
        so1[tid] = g_o[(b + 1) * HH + tid];
        wv[tid]  = Wv[tid];
    }
    __syncthreads();
    int m = tid;
    const float* oo = (b >= m) ? so1 : so0;
    float acc = 0.f;
    #pragma unroll 8
    for (int h = 0; h < HH; h++)
        acc += fast_tanh(g_cT[h * MM + m] + oo[h]) * wv[h];
    out[OFF_V + m * MB + b] = acc;
    float e = __expf(acc);
    red[tid] = e;
    __syncthreads();
    for (int s = 128; s > 0; s >>= 1) {
        if (tid < s) red[tid] += red[tid + s];
        __syncthreads();
    }
    float sumE = red[0];
    __syncthreads();
    float a = e / (sumE - e);
    g_alpha[m * MB + b] = a;
    red[tid] = a;
    __syncthreads();
    for (int s = 128; s > 0; s >>= 1) {
        if (tid < s) red[tid] += red[tid + s];
        __syncthreads();
    }
    if (tid == 0) g_colA[b] = red[0];
    __syncthreads();
}

// ---------------- phase 3 compute: tilda row m ----------------
__device__ void phase3(int m, float* __restrict__ out, float* sr, float* partial) {
    int tid = threadIdx.x;
    if (tid < MB) sr[tid] = g_colA[tid] - g_alpha[m * MB + tid];
    __syncthreads();
    int half = tid >> 7;
    int h    = tid & 127;
    float acc = 0.f;
    if (h < HH) {
        const float* rbase = out + OFF_R;
        int b0 = half ? 128 : 0;
        int b1 = half ? MB : 128;
        #pragma unroll 4
        for (int b = b0; b < b1; b++) {
            int j = b + (b >= m);
            acc += sr[b] * rbase[j * HH + h];
        }
    }
    if (half == 0 && h < HH) partial[h] = acc;
    __syncthreads();
    if (half == 1 && h < HH) out[OFF_T + m * HH + h] = acc + partial[h];
    __syncthreads();
}

// ---------------- single persistent kernel ----------------
__global__ __launch_bounds__(256) void kAll(const float* __restrict__ S_p,
                                            const int* __restrict__ spans,
                                            const int* __restrict__ passages,
                                            const float* __restrict__ Wb,
                                            const float* __restrict__ We,
                                            const float* __restrict__ Wc,
                                            const float* __restrict__ Wo,
                                            const float* __restrict__ Wv,
                                            float* __restrict__ out) {
    __shared__ __align__(16) float4 zblk[ZBYTES / 16];   // zeros for TMA stores
    __shared__ float shA[2 * DD];          // sb|se (p1) ; so0|so1+wv (p2)
    __shared__ float shB[MM + 8];          // rs (p1) ; red (p2) ; sr (p3)
    __shared__ float shC[HH + 4];          // partial (p3)
    __shared__ int   s_tmp;
    int bid = blockIdx.x;
    int tid = threadIdx.x;

    // init zero buffer once; fence for async-proxy reads (TMA)
    const float4 z = make_float4(0.f, 0.f, 0.f, 0.f);
    #pragma unroll
    for (int i = tid; i < ZBYTES / 16; i += 256) zblk[i] = z;
    asm volatile("fence.proxy.async.shared::cta;" ::: "memory");
    __syncthreads();
    uint32_t zbuf = smem_u32(zblk);

    if (bid < MM) {
        // p1 block for row m=bid
        phase1(bid, S_p, spans, passages, Wb, We, Wc, Wo, out,
               shA, shA + DD, shB);
        __threadfence();
        if (tid == 0) atomicAdd(&g_cnt1, 1);
        __syncthreads();
    } else if (bid < MM + MB) {
        // p2 block for column b=bid-256: wait for all p1, stealing meanwhile
        wait_phase(&g_cnt1, MM, S_p, spans, out, &s_tmp, zbuf);
        phase2(bid - MM, Wv, out, shA, shA + HH, shA + 2 * HH, shB);
        __threadfence();
        if (tid == 0) atomicAdd(&g_cnt2, 1);
        __syncthreads();
    }

    if (bid < MM) {
        // p3 reuses p1 blocks: wait for all p2, stealing meanwhile
        wait_phase(&g_cnt2, MB, S_p, spans, out, &s_tmp, zbuf);
        phase3(bid, out, shB, shC);
    }

    // drain remaining copy jobs
    while (steal_one(S_p, spans, out, &s_tmp, zbuf)) {}

    // all TMA bulk stores must complete before kernel exit
    if (tid == 0) asm volatile("cp.async.bulk.wait_group 0;" ::: "memory");

    // exit + self-reset for graph replay
    __syncthreads();
    if (tid == 0) {
        int d = atomicAdd(&g_done, 1);
        if (d == GRID - 1) {
            g_job  = 0;
            g_cnt1 = 0;
            g_cnt2 = 0;
            g_done = 0;
        }
    }
}

extern "C" void kernel_launch(void* const* d_in, const int* in_sizes, int n_in,
                              void* d_out, int out_size) {
    const float* S_p      = (const float*)d_in[0];
    const int*   spans    = (const int*)d_in[1];
    const int*   passages = (const int*)d_in[2];
    const float* Wb       = (const float*)d_in[3];
    const float* We       = (const float*)d_in[4];
    const float* Wc       = (const float*)d_in[5];
    const float* Wo       = (const float*)d_in[6];
    const float* Wv       = (const float*)d_in[7];
    float* out = (float*)d_out;

    kAll<<<GRID, 256>>>(S_p, spans, passages, Wb, We, Wc, Wo, Wv, out);
}